// round 16
// baseline (speedup 1.0000x reference)
#include <cuda_runtime.h>
#include <cuda_fp16.h>
#include <math.h>
#include <stdint.h>

#define BATCH 2
#define SEQ   2048
#define DIM   4096
#define NH    32
#define NKV   8
#define HD    128
#define MROWS 4096   // BATCH*SEQ
#define KVDIM 1024   // NKV*HD
#define KDIM  4096   // GEMM inner K
#define NQKV  (DIM + 2 * KVDIM)   // 6144 fused QKV output cols

// ---------------- scratch (zero-init .bss, no runtime allocation) ----------
__device__ __half g_xs [(size_t)MROWS * KDIM];
__device__ __half g_as [(size_t)MROWS * KDIM];
__device__ __half g_wqs[(size_t)DIM   * KDIM];
__device__ __half g_wks[(size_t)KVDIM * KDIM];
__device__ __half g_wvs[(size_t)KVDIM * KDIM];
__device__ __half g_wos[(size_t)DIM   * KDIM];

// attention fp16 operands (written by fused QKV epilogue)
__device__ __half g_qs2[(size_t)BATCH * NH  * SEQ * 256];  // Q (hi,lo) interleaved
__device__ __half g_ks2[(size_t)BATCH * NKV * SEQ * 256];  // K (k,k) dup
__device__ __half g_vs2[(size_t)BATCH * NKV * SEQ * HD];   // V plain

// ---------------- helpers ---------------------------------------------------
__device__ __forceinline__ uint32_t smem_u32(const void* p) {
    return (uint32_t)__cvta_generic_to_shared(p);
}
__device__ __forceinline__ void cp_async16(uint32_t dst, const void* src) {
    asm volatile("cp.async.cg.shared.global [%0], [%1], 16;" :: "r"(dst), "l"(src) : "memory");
}
__device__ __forceinline__ void cp_commit() {
    asm volatile("cp.async.commit_group;" ::: "memory");
}

#define LDSM_X4(r0, r1, r2, r3, addr) \
    asm volatile("ldmatrix.sync.aligned.m8n8.x4.shared.b16 {%0,%1,%2,%3}, [%4];" \
                 : "=r"(r0), "=r"(r1), "=r"(r2), "=r"(r3) : "r"(addr))

#define LDSM_X4_T(r0, r1, r2, r3, addr) \
    asm volatile("ldmatrix.sync.aligned.m8n8.x4.trans.shared.b16 {%0,%1,%2,%3}, [%4];" \
                 : "=r"(r0), "=r"(r1), "=r"(r2), "=r"(r3) : "r"(addr))

#define MMA_F16(d, a, b0v, b1v) \
    asm volatile("mma.sync.aligned.m16n8k16.row.col.f32.f16.f16.f32 " \
                 "{%0,%1,%2,%3}, {%4,%5,%6,%7}, {%8,%9}, {%0,%1,%2,%3};" \
                 : "+f"((d)[0]), "+f"((d)[1]), "+f"((d)[2]), "+f"((d)[3]) \
                 : "r"((a)[0]), "r"((a)[1]), "r"((a)[2]), "r"((a)[3]), \
                   "r"(b0v), "r"(b1v))

// ---------------------------------------------------------------------------
// fp32 -> fp16, 16 floats/thread (MLP 4), coalesced
// ---------------------------------------------------------------------------
__global__ void __launch_bounds__(256) cvt_f16(
    const float* __restrict__ src, __half* __restrict__ dst)
{
    size_t t = (size_t)blockIdx.x * 256 + threadIdx.x;
    float4 v0 = *(const float4*)&src[t * 16];
    float4 v1 = *(const float4*)&src[t * 16 + 4];
    float4 v2 = *(const float4*)&src[t * 16 + 8];
    float4 v3 = *(const float4*)&src[t * 16 + 12];
    float f[16] = {v0.x,v0.y,v0.z,v0.w, v1.x,v1.y,v1.z,v1.w,
                   v2.x,v2.y,v2.z,v2.w, v3.x,v3.y,v3.z,v3.w};
    __align__(16) __half h[16];
#pragma unroll
    for (int j = 0; j < 16; j++) h[j] = __float2half_rn(f[j]);
    uint4* dp = (uint4*)&dst[t * 16];
    dp[0] = *(uint4*)&h[0];
    dp[1] = *(uint4*)&h[8];
}

// ---------------------------------------------------------------------------
// Fused QKV GEMM (R13 loop, proven). B + epilogue selected per-CTA by bn:
//   bn < 4096            -> wq, rope+scale -> g_qs2 (hi,lo)
//   4096 <= bn < 5120    -> wk, rope       -> g_ks2 (k,k)
//   else                 -> wv             -> g_vs2
// ---------------------------------------------------------------------------
#define BKC         32
#define ROW_BYTES   80
#define STAGE_BYTES (256 * ROW_BYTES)
#define NSTAGE      4
#define GSMEM       (NSTAGE * STAGE_BYTES)
#define NITER       (KDIM / BKC)          // 128

__global__ void __launch_bounds__(256) gemm_qkv(
    const __half* __restrict__ A,
    const float* __restrict__ fc, const float* __restrict__ fs)
{
    extern __shared__ __align__(1024) char smem[];
    const uint32_t sbase = smem_u32(smem);

    const int bm = blockIdx.y * 128;
    const int bn = blockIdx.x * 128;
    const int tid = threadIdx.x;
    const int wid = tid >> 5;
    const int lane = tid & 31;
    const int wm = wid & 3;
    const int wn = wid >> 2;

    // per-CTA B select (uniform)
    int epi, bnl;
    const __half* Bsel;
    if (bn < DIM)                { Bsel = g_wqs; epi = 1; bnl = bn; }
    else if (bn < DIM + KVDIM)   { Bsel = g_wks; epi = 2; bnl = bn - DIM; }
    else                         { Bsel = g_wvs; epi = 3; bnl = bn - DIM - KVDIM; }

    const __half* ga0 = A    + (size_t)bm  * KDIM;
    const __half* gb0 = Bsel + (size_t)bnl * KDIM;

    const int lc = tid & 3;
    const int lr = tid >> 2;

    auto load_stage = [&](int s, int chunk) {
        const uint32_t sa = sbase + (uint32_t)s * STAGE_BYTES;
        const size_t koff = (size_t)chunk * BKC + lc * 8;
#pragma unroll
        for (int j = 0; j < 4; j++) {
            int r = lr + j * 64;
            const __half* src = (r < 128)
                ? ga0 + (size_t)r * KDIM + koff
                : gb0 + (size_t)(r - 128) * KDIM + koff;
            cp_async16(sa + (uint32_t)(r * ROW_BYTES + lc * 16), src);
        }
        cp_commit();
    };

    float d[2][8][4];
#pragma unroll
    for (int mi = 0; mi < 2; mi++)
#pragma unroll
        for (int nj = 0; nj < 8; nj++)
#pragma unroll
            for (int q = 0; q < 4; q++) d[mi][nj][q] = 0.0f;

    const int grp  = lane >> 3;
    const int lrow = lane & 7;
    const int a_r = lrow + ((grp & 1) << 3);
    const int a_c = (grp >> 1) << 3;
    const int b_r = lrow + ((grp >> 1) << 3);
    const int b_c = (grp & 1) << 3;

    load_stage(0, 0);
    load_stage(1, 1);
    load_stage(2, 2);

    for (int i = 0; i < NITER; i++) {
        const int s = i & (NSTAGE - 1);
        asm volatile("cp.async.wait_group %0;" :: "n"(NSTAGE - 2) : "memory");
        __syncthreads();
        if (i + 3 < NITER) load_stage((i + 3) & (NSTAGE - 1), i + 3);
        else cp_commit();

        const uint32_t aB = sbase + (uint32_t)s * STAGE_BYTES;
        const uint32_t bB = aB + 128 * ROW_BYTES;
#pragma unroll
        for (int step = 0; step < 2; step++) {
            uint32_t af[2][4];
#pragma unroll
            for (int mi = 0; mi < 2; mi++) {
                uint32_t addr = aB + (uint32_t)((wm * 32 + mi * 16 + a_r) * ROW_BYTES
                                                + (step * 16 + a_c) * 2);
                LDSM_X4(af[mi][0], af[mi][1], af[mi][2], af[mi][3], addr);
            }
#pragma unroll
            for (int njp = 0; njp < 4; njp++) {
                uint32_t b0, b1, b2, b3;
                uint32_t addr = bB + (uint32_t)((wn * 64 + njp * 16 + b_r) * ROW_BYTES
                                                + (step * 16 + b_c) * 2);
                LDSM_X4(b0, b1, b2, b3, addr);
#pragma unroll
                for (int mi = 0; mi < 2; mi++) {
                    MMA_F16(d[mi][2 * njp],     af[mi], b0, b1);
                    MMA_F16(d[mi][2 * njp + 1], af[mi], b2, b3);
                }
            }
        }
    }

    // ------------------- epilogue (runtime epi, uniform per CTA) ------------
    const int er = lane >> 2;
    const int ec = (lane & 3) * 2;
#pragma unroll
    for (int mi = 0; mi < 2; mi++) {
#pragma unroll
        for (int nj = 0; nj < 8; nj++) {
            const int r0  = bm + wm * 32 + mi * 16 + er;
            const int c0l = bnl + wn * 64 + nj * 8 + ec;   // local col (even)
            const int h = c0l >> 7, dl = c0l & 127;

            if (epi == 3) {
#pragma unroll
                for (int half = 0; half < 2; half++) {
                    int m = r0 + half * 8;
                    int b = m >> 11, t = m & (SEQ - 1);
                    __half2 hv = __floats2half2_rn(d[mi][nj][2 * half], d[mi][nj][2 * half + 1]);
                    *(__half2*)&g_vs2[((size_t)(b * NKV + h) * SEQ + t) * HD + dl] = hv;
                }
            } else {
                const int ip = dl >> 1;
#pragma unroll
                for (int half = 0; half < 2; half++) {
                    int m = r0 + half * 8;
                    int b = m >> 11, s = m & (SEQ - 1);
                    float cv = fc[s * 64 + ip];
                    float sv = fs[s * 64 + ip];
                    float xr = d[mi][nj][2 * half], xi = d[mi][nj][2 * half + 1];
                    float rr = xr * cv - xi * sv;
                    float ri = xr * sv + xi * cv;
                    __align__(8) __half o[4];
                    if (epi == 1) {
                        rr *= 0.08838834764831845f; ri *= 0.08838834764831845f;
                        __half hr = __float2half_rn(rr);
                        __half hi = __float2half_rn(ri);
                        o[0] = hr; o[1] = __float2half_rn(rr - __half2float(hr));
                        o[2] = hi; o[3] = __float2half_rn(ri - __half2float(hi));
                    } else {
                        __half hr = __float2half_rn(rr);
                        __half hi = __float2half_rn(ri);
                        o[0] = hr; o[1] = hr; o[2] = hi; o[3] = hi;
                    }
                    size_t rowo = (epi == 1)
                        ? ((size_t)(b * NH  + h) * SEQ + s)
                        : ((size_t)(b * NKV + h) * SEQ + s);
                    __half* dp = (epi == 1 ? g_qs2 : g_ks2) + rowo * 256 + dl * 2;
                    *(uint2*)dp = *(uint2*)o;
                }
            }
        }
    }
}

// ---------------------------------------------------------------------------
// Output projection GEMM (fp32 epilogue; R13 loop, proven)
// ---------------------------------------------------------------------------
__global__ void __launch_bounds__(256) gemm_out(
    const __half* __restrict__ A, const __half* __restrict__ Bm,
    float* __restrict__ C, int N)
{
    extern __shared__ __align__(1024) char smem[];
    const uint32_t sbase = smem_u32(smem);

    const int bm = blockIdx.y * 128;
    const int bn = blockIdx.x * 128;
    const int tid = threadIdx.x;
    const int wid = tid >> 5;
    const int lane = tid & 31;
    const int wm = wid & 3;
    const int wn = wid >> 2;

    const __half* ga0 = A  + (size_t)bm * KDIM;
    const __half* gb0 = Bm + (size_t)bn * KDIM;

    const int lc = tid & 3;
    const int lr = tid >> 2;

    auto load_stage = [&](int s, int chunk) {
        const uint32_t sa = sbase + (uint32_t)s * STAGE_BYTES;
        const size_t koff = (size_t)chunk * BKC + lc * 8;
#pragma unroll
        for (int j = 0; j < 4; j++) {
            int r = lr + j * 64;
            const __half* src = (r < 128)
                ? ga0 + (size_t)r * KDIM + koff
                : gb0 + (size_t)(r - 128) * KDIM + koff;
            cp_async16(sa + (uint32_t)(r * ROW_BYTES + lc * 16), src);
        }
        cp_commit();
    };

    float d[2][8][4];
#pragma unroll
    for (int mi = 0; mi < 2; mi++)
#pragma unroll
        for (int nj = 0; nj < 8; nj++)
#pragma unroll
            for (int q = 0; q < 4; q++) d[mi][nj][q] = 0.0f;

    const int grp  = lane >> 3;
    const int lrow = lane & 7;
    const int a_r = lrow + ((grp & 1) << 3);
    const int a_c = (grp >> 1) << 3;
    const int b_r = lrow + ((grp >> 1) << 3);
    const int b_c = (grp & 1) << 3;

    load_stage(0, 0);
    load_stage(1, 1);
    load_stage(2, 2);

    for (int i = 0; i < NITER; i++) {
        const int s = i & (NSTAGE - 1);
        asm volatile("cp.async.wait_group %0;" :: "n"(NSTAGE - 2) : "memory");
        __syncthreads();
        if (i + 3 < NITER) load_stage((i + 3) & (NSTAGE - 1), i + 3);
        else cp_commit();

        const uint32_t aB = sbase + (uint32_t)s * STAGE_BYTES;
        const uint32_t bB = aB + 128 * ROW_BYTES;
#pragma unroll
        for (int step = 0; step < 2; step++) {
            uint32_t af[2][4];
#pragma unroll
            for (int mi = 0; mi < 2; mi++) {
                uint32_t addr = aB + (uint32_t)((wm * 32 + mi * 16 + a_r) * ROW_BYTES
                                                + (step * 16 + a_c) * 2);
                LDSM_X4(af[mi][0], af[mi][1], af[mi][2], af[mi][3], addr);
            }
#pragma unroll
            for (int njp = 0; njp < 4; njp++) {
                uint32_t b0, b1, b2, b3;
                uint32_t addr = bB + (uint32_t)((wn * 64 + njp * 16 + b_r) * ROW_BYTES
                                                + (step * 16 + b_c) * 2);
                LDSM_X4(b0, b1, b2, b3, addr);
#pragma unroll
                for (int mi = 0; mi < 2; mi++) {
                    MMA_F16(d[mi][2 * njp],     af[mi], b0, b1);
                    MMA_F16(d[mi][2 * njp + 1], af[mi], b2, b3);
                }
            }
        }
    }

    const int er = lane >> 2;
    const int ec = (lane & 3) * 2;
#pragma unroll
    for (int mi = 0; mi < 2; mi++) {
#pragma unroll
        for (int nj = 0; nj < 8; nj++) {
            int r0 = bm + wm * 32 + mi * 16 + er;
            int c0 = bn + wn * 64 + nj * 8 + ec;
            *(float2*)&C[(size_t)r0 * N + c0]       = make_float2(d[mi][nj][0], d[mi][nj][1]);
            *(float2*)&C[(size_t)(r0 + 8) * N + c0] = make_float2(d[mi][nj][2], d[mi][nj][3]);
        }
    }
}

// ---------------------------------------------------------------------------
// fp16 causal flash attention (R13/R14, proven); epilogue writes fp16 g_as.
// ---------------------------------------------------------------------------
#define SQ_STR   528
#define SK_STR   528
#define SV_STR   272
#define SP_STR   144
#define SQ_OFF   0
#define SK_OFF   33792
#define SV_OFF   67584
#define SP_OFF   84992
#define ATT_SMEM 94208

__global__ void __launch_bounds__(256) attn_mma(
    const __half* __restrict__ Qs, const __half* __restrict__ Ks,
    const __half* __restrict__ Vs, __half* __restrict__ Oas)
{
    extern __shared__ __align__(1024) char smem[];
    const uint32_t sQ = smem_u32(smem) + SQ_OFF;
    const uint32_t sK = smem_u32(smem) + SK_OFF;
    const uint32_t sV = smem_u32(smem) + SV_OFF;
    const uint32_t sP = smem_u32(smem) + SP_OFF;
    float* mergeO = (float*)smem;
    float* mergeM = (float*)(smem + 32768);
    float* mergeL = (float*)(smem + 32768 + 256);

    const int qi = (SEQ / 64 - 1) - blockIdx.x;
    const int bh = blockIdx.y;
    const int b = bh >> 5, h = bh & 31, kvh = h >> 2;
    const int q0 = qi * 64;
    const int tid = threadIdx.x;
    const int wid = tid >> 5, lane = tid & 31;
    const int wm = wid & 3, wn = wid >> 2;
    const int grp = lane >> 3, lrow = lane & 7;

    const __half* gk = Ks + ((size_t)(b * NKV + kvh) * SEQ) * 256;
    const __half* gv = Vs + ((size_t)(b * NKV + kvh) * SEQ) * HD;

    auto load_k = [&](int t0) {
#pragma unroll
        for (int j = 0; j < 8; j++) {
            int id = tid + j * 256;
            int r = id >> 5, c = id & 31;
            cp_async16(sK + (uint32_t)(r * SK_STR + c * 16),
                       gk + ((size_t)(t0 + r)) * 256 + c * 8);
        }
        cp_commit();
    };
    auto load_v = [&](int t0) {
#pragma unroll
        for (int j = 0; j < 4; j++) {
            int id = tid + j * 256;
            int r = id >> 4, c = id & 15;
            cp_async16(sV + (uint32_t)(r * SV_STR + c * 16),
                       gv + ((size_t)(t0 + r)) * HD + c * 8);
        }
        cp_commit();
    };

    const __half* gq = Qs + ((size_t)(b * NH + h) * SEQ + q0) * 256;
#pragma unroll
    for (int j = 0; j < 8; j++) {
        int id = tid + j * 256;
        int r = id >> 5, c = id & 31;
        cp_async16(sQ + (uint32_t)(r * SQ_STR + c * 16), gq + (size_t)r * 256 + c * 8);
    }
    cp_commit();
    load_k(0);
    load_v(0);

    float m0 = -1e30f, m1 = -1e30f, l0 = 0.0f, l1 = 0.0f;
    float Oc[16][4];
#pragma unroll
    for (int j = 0; j < 16; j++)
#pragma unroll
        for (int q = 0; q < 4; q++) Oc[j][q] = 0.0f;

    const int ra = wm * 16 + (lane >> 2);

    for (int kt = 0; kt <= qi; kt++) {
        asm volatile("cp.async.wait_group 0;" ::: "memory");
        __syncthreads();

        float Sa[4][4];
#pragma unroll
        for (int nt = 0; nt < 4; nt++)
#pragma unroll
            for (int q = 0; q < 4; q++) Sa[nt][q] = 0.0f;

#pragma unroll
        for (int ks = 0; ks < 16; ks++) {
            uint32_t A[4];
            uint32_t aaddr = sQ + (uint32_t)((wm * 16 + lrow + ((grp & 1) << 3)) * SQ_STR
                                             + (ks * 16 + ((grp >> 1) << 3)) * 2);
            LDSM_X4(A[0], A[1], A[2], A[3], aaddr);
#pragma unroll
            for (int ntp = 0; ntp < 2; ntp++) {
                uint32_t b0, b1, b2, b3;
                uint32_t baddr = sK + (uint32_t)((wn * 32 + ntp * 16 + lrow + ((grp >> 1) << 3)) * SK_STR
                                                 + (ks * 16 + ((grp & 1) << 3)) * 2);
                LDSM_X4(b0, b1, b2, b3, baddr);
                MMA_F16(Sa[2 * ntp],     A, b0, b1);
                MMA_F16(Sa[2 * ntp + 1], A, b2, b3);
            }
        }

        __syncthreads();
        if (kt < qi) load_k((kt + 1) * 64);

        if (kt == qi) {
#pragma unroll
            for (int nt = 0; nt < 4; nt++) {
                int tb = wn * 32 + nt * 8 + 2 * (lane & 3);
                if (tb     > ra)     Sa[nt][0] = -1e30f;
                if (tb + 1 > ra)     Sa[nt][1] = -1e30f;
                if (tb     > ra + 8) Sa[nt][2] = -1e30f;
                if (tb + 1 > ra + 8) Sa[nt][3] = -1e30f;
            }
        }

        float hm0 = -1e30f, hm1 = -1e30f;
#pragma unroll
        for (int nt = 0; nt < 4; nt++) {
            hm0 = fmaxf(hm0, fmaxf(Sa[nt][0], Sa[nt][1]));
            hm1 = fmaxf(hm1, fmaxf(Sa[nt][2], Sa[nt][3]));
        }
        hm0 = fmaxf(hm0, __shfl_xor_sync(0xffffffffu, hm0, 1));
        hm0 = fmaxf(hm0, __shfl_xor_sync(0xffffffffu, hm0, 2));
        hm1 = fmaxf(hm1, __shfl_xor_sync(0xffffffffu, hm1, 1));
        hm1 = fmaxf(hm1, __shfl_xor_sync(0xffffffffu, hm1, 2));

        float mn0 = fmaxf(m0, hm0), mn1 = fmaxf(m1, hm1);
        float al0 = __expf(m0 - mn0), al1 = __expf(m1 - mn1);
        m0 = mn0; m1 = mn1;

        float hs0 = 0.0f, hs1 = 0.0f;
#pragma unroll
        for (int nt = 0; nt < 4; nt++) {
            Sa[nt][0] = __expf(Sa[nt][0] - mn0); hs0 += Sa[nt][0];
            Sa[nt][1] = __expf(Sa[nt][1] - mn0); hs0 += Sa[nt][1];
            Sa[nt][2] = __expf(Sa[nt][2] - mn1); hs1 += Sa[nt][2];
            Sa[nt][3] = __expf(Sa[nt][3] - mn1); hs1 += Sa[nt][3];
        }
        hs0 += __shfl_xor_sync(0xffffffffu, hs0, 1);
        hs0 += __shfl_xor_sync(0xffffffffu, hs0, 2);
        hs1 += __shfl_xor_sync(0xffffffffu, hs1, 1);
        hs1 += __shfl_xor_sync(0xffffffffu, hs1, 2);
        l0 = l0 * al0 + hs0;
        l1 = l1 * al1 + hs1;
#pragma unroll
        for (int j = 0; j < 16; j++) {
            Oc[j][0] *= al0; Oc[j][1] *= al0;
            Oc[j][2] *= al1; Oc[j][3] *= al1;
        }

        __syncwarp();
#pragma unroll
        for (int nt = 0; nt < 4; nt++) {
            int tl0 = wn * 32 + nt * 8 + 2 * (lane & 3);
#pragma unroll
            for (int q = 0; q < 4; q++) {
                int row = ra + ((q >> 1) << 3);
                int t = tl0 + (q & 1);
                uint16_t pv = __half_as_ushort(__float2half_rn(Sa[nt][q]));
                uint32_t ad = sP + (uint32_t)(row * SP_STR + t * 2);
                asm volatile("st.shared.u16 [%0], %1;" :: "r"(ad), "h"(pv));
            }
        }
        __syncwarp();

#pragma unroll
        for (int ks2 = 0; ks2 < 2; ks2++) {
            uint32_t A[4];
            uint32_t aaddr = sP + (uint32_t)((wm * 16 + lrow + ((grp & 1) << 3)) * SP_STR
                                             + (wn * 32 + ks2 * 16 + ((grp >> 1) << 3)) * 2);
            LDSM_X4(A[0], A[1], A[2], A[3], aaddr);
#pragma unroll
            for (int ntp = 0; ntp < 8; ntp++) {
                uint32_t b0, b1, b2, b3;
                uint32_t baddr = sV + (uint32_t)((wn * 32 + ks2 * 16 + lrow + ((grp & 1) << 3)) * SV_STR
                                                 + (ntp * 16 + ((grp >> 1) << 3)) * 2);
                LDSM_X4_T(b0, b1, b2, b3, baddr);
                MMA_F16(Oc[2 * ntp],     A, b0, b1);
                MMA_F16(Oc[2 * ntp + 1], A, b2, b3);
            }
        }

        __syncthreads();
        if (kt < qi) load_v((kt + 1) * 64);
    }

    __syncthreads();
    if (wn == 1) {
#pragma unroll
        for (int nt = 0; nt < 16; nt++) {
            int col = nt * 8 + 2 * (lane & 3);
            *(float2*)&mergeO[ra * 128 + col]       = make_float2(Oc[nt][0], Oc[nt][1]);
            *(float2*)&mergeO[(ra + 8) * 128 + col] = make_float2(Oc[nt][2], Oc[nt][3]);
        }
        if ((lane & 3) == 0) {
            mergeM[ra] = m0;     mergeM[ra + 8] = m1;
            mergeL[ra] = l0;     mergeL[ra + 8] = l1;
        }
    }
    __syncthreads();
    if (wn == 0) {
        float M1a = mergeM[ra],     L1a = mergeL[ra];
        float M1b = mergeM[ra + 8], L1b = mergeL[ra + 8];
        float Ma = fmaxf(m0, M1a);
        float w0a = __expf(m0 - Ma), w1a = __expf(M1a - Ma);
        float inva = 1.0f / (l0 * w0a + L1a * w1a);
        float Mb = fmaxf(m1, M1b);
        float w0b = __expf(m1 - Mb), w1b = __expf(M1b - Mb);
        float invb = 1.0f / (l1 * w0b + L1b * w1b);

        const size_t r0g = (size_t)(b * SEQ + q0 + ra);
#pragma unroll
        for (int nt = 0; nt < 16; nt++) {
            int col = nt * 8 + 2 * (lane & 3);
            float2 o1a = *(float2*)&mergeO[ra * 128 + col];
            float2 o1b = *(float2*)&mergeO[(ra + 8) * 128 + col];
            float oa0 = (Oc[nt][0] * w0a + o1a.x * w1a) * inva;
            float oa1 = (Oc[nt][1] * w0a + o1a.y * w1a) * inva;
            float ob0 = (Oc[nt][2] * w0b + o1b.x * w1b) * invb;
            float ob1 = (Oc[nt][3] * w0b + o1b.y * w1b) * invb;
            int cg = h * HD + col;
            *(__half2*)&Oas[r0g * DIM + cg]       = __floats2half2_rn(oa0, oa1);
            *(__half2*)&Oas[(r0g + 8) * DIM + cg] = __floats2half2_rn(ob0, ob1);
        }
    }
}

// ---------------------------------------------------------------------------
extern "C" void kernel_launch(void* const* d_in, const int* in_sizes, int n_in,
                              void* d_out, int out_size)
{
    const float* x  = (const float*)d_in[0];
    const float* wq = (const float*)d_in[1];
    const float* wk = (const float*)d_in[2];
    const float* wv = (const float*)d_in[3];
    const float* wo = (const float*)d_in[4];
    const float* fc = (const float*)d_in[5];
    const float* fs = (const float*)d_in[6];
    float* out = (float*)d_out;

    __half *xs, *as, *wqs, *wks, *wvs, *wos, *qs2, *ks2, *vs2;
    cudaGetSymbolAddress((void**)&xs, g_xs);
    cudaGetSymbolAddress((void**)&as, g_as);
    cudaGetSymbolAddress((void**)&wqs, g_wqs);
    cudaGetSymbolAddress((void**)&wks, g_wks);
    cudaGetSymbolAddress((void**)&wvs, g_wvs);
    cudaGetSymbolAddress((void**)&wos, g_wos);
    cudaGetSymbolAddress((void**)&qs2, g_qs2);
    cudaGetSymbolAddress((void**)&ks2, g_ks2);
    cudaGetSymbolAddress((void**)&vs2, g_vs2);

    cudaFuncSetAttribute(gemm_qkv, cudaFuncAttributeMaxDynamicSharedMemorySize, GSMEM);
    cudaFuncSetAttribute(gemm_out, cudaFuncAttributeMaxDynamicSharedMemorySize, GSMEM);
    cudaFuncSetAttribute(attn_mma, cudaFuncAttributeMaxDynamicSharedMemorySize, GSMEM > ATT_SMEM ? GSMEM : ATT_SMEM);

    // fp16 conversions (16 floats/thread)
    cvt_f16<<<(MROWS * KDIM / 16) / 256, 256>>>(x,  xs);
    cvt_f16<<<(DIM   * KDIM / 16) / 256, 256>>>(wq, wqs);
    cvt_f16<<<(KVDIM * KDIM / 16) / 256, 256>>>(wk, wks);
    cvt_f16<<<(KVDIM * KDIM / 16) / 256, 256>>>(wv, wvs);
    cvt_f16<<<(DIM   * KDIM / 16) / 256, 256>>>(wo, wos);

    // Fused QKV projection with rope/pack epilogues
    gemm_qkv<<<dim3(NQKV / 128, MROWS / 128), 256, GSMEM>>>(xs, fc, fs);

    // fp16 flash attention (epilogue writes fp16 g_as)
    attn_mma<<<dim3(SEQ / 64, BATCH * NH), 256, ATT_SMEM>>>(qs2, ks2, vs2, as);

    // Output projection (fp32 epilogue)
    gemm_out<<<dim3(DIM / 128, MROWS / 128), 256, GSMEM>>>(as, wos, out, DIM);
}

// round 17
// speedup vs baseline: 1.5557x; 1.5557x over previous
#include <cuda_runtime.h>
#include <cuda_fp16.h>
#include <math.h>
#include <stdint.h>

#define BATCH 2
#define SEQ   2048
#define DIM   4096
#define NH    32
#define NKV   8
#define HD    128
#define MROWS 4096   // BATCH*SEQ
#define KVDIM 1024   // NKV*HD
#define KDIM  4096   // GEMM inner K

// ---------------- scratch (zero-init .bss, no runtime allocation) ----------
// plain fp16 GEMM operands
__device__ __half g_xs [(size_t)MROWS * KDIM];
__device__ __half g_as [(size_t)MROWS * KDIM];   // attn out, fp16, written by attn epilogue
__device__ __half g_wqs[(size_t)DIM   * KDIM];
__device__ __half g_wks[(size_t)KVDIM * KDIM];
__device__ __half g_wvs[(size_t)KVDIM * KDIM];
__device__ __half g_wos[(size_t)DIM   * KDIM];

// attention fp16 operands (written directly by QKV gemm epilogues)
__device__ __half g_qs2[(size_t)BATCH * NH  * SEQ * 256];  // Q (hi,lo) interleaved
__device__ __half g_ks2[(size_t)BATCH * NKV * SEQ * 256];  // K (k,k) dup
__device__ __half g_vs2[(size_t)BATCH * NKV * SEQ * HD];   // V plain

// ---------------- helpers ---------------------------------------------------
__device__ __forceinline__ uint32_t smem_u32(const void* p) {
    return (uint32_t)__cvta_generic_to_shared(p);
}
__device__ __forceinline__ void cp_async16(uint32_t dst, const void* src) {
    asm volatile("cp.async.cg.shared.global [%0], [%1], 16;" :: "r"(dst), "l"(src) : "memory");
}
__device__ __forceinline__ void cp_commit() {
    asm volatile("cp.async.commit_group;" ::: "memory");
}

#define LDSM_X4(r0, r1, r2, r3, addr) \
    asm volatile("ldmatrix.sync.aligned.m8n8.x4.shared.b16 {%0,%1,%2,%3}, [%4];" \
                 : "=r"(r0), "=r"(r1), "=r"(r2), "=r"(r3) : "r"(addr))

#define LDSM_X4_T(r0, r1, r2, r3, addr) \
    asm volatile("ldmatrix.sync.aligned.m8n8.x4.trans.shared.b16 {%0,%1,%2,%3}, [%4];" \
                 : "=r"(r0), "=r"(r1), "=r"(r2), "=r"(r3) : "r"(addr))

#define MMA_F16(d, a, b0v, b1v) \
    asm volatile("mma.sync.aligned.m16n8k16.row.col.f32.f16.f16.f32 " \
                 "{%0,%1,%2,%3}, {%4,%5,%6,%7}, {%8,%9}, {%0,%1,%2,%3};" \
                 : "+f"((d)[0]), "+f"((d)[1]), "+f"((d)[2]), "+f"((d)[3]) \
                 : "r"((a)[0]), "r"((a)[1]), "r"((a)[2]), "r"((a)[3]), \
                   "r"(b0v), "r"(b1v))

// ---------------------------------------------------------------------------
// fp32 -> fp16, coalesced (inputs/weights only)
// ---------------------------------------------------------------------------
__global__ void __launch_bounds__(256) cvt_f16(
    const float* __restrict__ src, __half* __restrict__ dst)
{
    size_t t = (size_t)blockIdx.x * 256 + threadIdx.x;
    float4 v0 = *(const float4*)&src[t * 8];
    float4 v1 = *(const float4*)&src[t * 8 + 4];
    float f[8] = {v0.x, v0.y, v0.z, v0.w, v1.x, v1.y, v1.z, v1.w};
    __align__(16) __half h[8];
#pragma unroll
    for (int j = 0; j < 8; j++) h[j] = __float2half_rn(f[j]);
    *(uint4*)&dst[t * 8] = *(uint4*)h;
}

// ---------------------------------------------------------------------------
// fp16 HMMA GEMM (R13 loop, proven). EPI: 0 = fp32 C store (final out);
// 1 = Q rope+scale -> g_qs2 (hi,lo); 2 = K rope -> g_ks2 (k,k); 3 = V -> g_vs2.
// ---------------------------------------------------------------------------
#define BKC         32
#define ROW_BYTES   80
#define STAGE_BYTES (256 * ROW_BYTES)
#define NSTAGE      4
#define GSMEM       (NSTAGE * STAGE_BYTES)
#define NITER       (KDIM / BKC)          // 128

template <int EPI>
__global__ void __launch_bounds__(256) gemm_hmma(
    const __half* __restrict__ A, const __half* __restrict__ Bm,
    float* __restrict__ C, const float* __restrict__ fc,
    const float* __restrict__ fs, int N)
{
    extern __shared__ __align__(1024) char smem[];
    const uint32_t sbase = smem_u32(smem);

    const int bm = blockIdx.y * 128;
    const int bn = blockIdx.x * 128;
    const int tid = threadIdx.x;
    const int wid = tid >> 5;
    const int lane = tid & 31;
    const int wm = wid & 3;
    const int wn = wid >> 2;

    const __half* ga0 = A  + (size_t)bm * KDIM;
    const __half* gb0 = Bm + (size_t)bn * KDIM;

    const int lc = tid & 3;
    const int lr = tid >> 2;

    auto load_stage = [&](int s, int chunk) {
        const uint32_t sa = sbase + (uint32_t)s * STAGE_BYTES;
        const size_t koff = (size_t)chunk * BKC + lc * 8;
#pragma unroll
        for (int j = 0; j < 4; j++) {
            int r = lr + j * 64;
            const __half* src = (r < 128)
                ? ga0 + (size_t)r * KDIM + koff
                : gb0 + (size_t)(r - 128) * KDIM + koff;
            cp_async16(sa + (uint32_t)(r * ROW_BYTES + lc * 16), src);
        }
        cp_commit();
    };

    float d[2][8][4];
#pragma unroll
    for (int mi = 0; mi < 2; mi++)
#pragma unroll
        for (int nj = 0; nj < 8; nj++)
#pragma unroll
            for (int q = 0; q < 4; q++) d[mi][nj][q] = 0.0f;

    const int grp  = lane >> 3;
    const int lrow = lane & 7;
    const int a_r = lrow + ((grp & 1) << 3);
    const int a_c = (grp >> 1) << 3;
    const int b_r = lrow + ((grp >> 1) << 3);
    const int b_c = (grp & 1) << 3;

    load_stage(0, 0);
    load_stage(1, 1);
    load_stage(2, 2);

    for (int i = 0; i < NITER; i++) {
        const int s = i & (NSTAGE - 1);
        asm volatile("cp.async.wait_group %0;" :: "n"(NSTAGE - 2) : "memory");
        __syncthreads();
        if (i + 3 < NITER) load_stage((i + 3) & (NSTAGE - 1), i + 3);
        else cp_commit();

        const uint32_t aB = sbase + (uint32_t)s * STAGE_BYTES;
        const uint32_t bB = aB + 128 * ROW_BYTES;
#pragma unroll
        for (int step = 0; step < 2; step++) {
            uint32_t af[2][4];
#pragma unroll
            for (int mi = 0; mi < 2; mi++) {
                uint32_t addr = aB + (uint32_t)((wm * 32 + mi * 16 + a_r) * ROW_BYTES
                                                + (step * 16 + a_c) * 2);
                LDSM_X4(af[mi][0], af[mi][1], af[mi][2], af[mi][3], addr);
            }
#pragma unroll
            for (int njp = 0; njp < 4; njp++) {
                uint32_t b0, b1, b2, b3;
                uint32_t addr = bB + (uint32_t)((wn * 64 + njp * 16 + b_r) * ROW_BYTES
                                                + (step * 16 + b_c) * 2);
                LDSM_X4(b0, b1, b2, b3, addr);
#pragma unroll
                for (int mi = 0; mi < 2; mi++) {
                    MMA_F16(d[mi][2 * njp],     af[mi], b0, b1);
                    MMA_F16(d[mi][2 * njp + 1], af[mi], b2, b3);
                }
            }
        }
    }

    // ------------------- epilogue -------------------
    const int er = lane >> 2;
    const int ec = (lane & 3) * 2;
#pragma unroll
    for (int mi = 0; mi < 2; mi++) {
#pragma unroll
        for (int nj = 0; nj < 8; nj++) {
            const int r0 = bm + wm * 32 + mi * 16 + er;   // global row (m)
            const int c0 = bn + wn * 64 + nj * 8 + ec;    // global col (even)

            if (EPI == 0) {
                *(float2*)&C[(size_t)r0 * N + c0]       = make_float2(d[mi][nj][0], d[mi][nj][1]);
                *(float2*)&C[(size_t)(r0 + 8) * N + c0] = make_float2(d[mi][nj][2], d[mi][nj][3]);
            } else if (EPI == 3) {
                const int kv = c0 >> 7, dl = c0 & 127;
#pragma unroll
                for (int half = 0; half < 2; half++) {
                    int m = r0 + half * 8;
                    int b = m >> 11, t = m & (SEQ - 1);
                    __half2 hv = __floats2half2_rn(d[mi][nj][2 * half], d[mi][nj][2 * half + 1]);
                    *(__half2*)&g_vs2[((size_t)(b * NKV + kv) * SEQ + t) * HD + dl] = hv;
                }
            } else {
                // Q (EPI==1) / K (EPI==2): rope applied to the (c0, c0+1) pair
                const int h = c0 >> 7, dl = c0 & 127;
                const int ip = dl >> 1;
#pragma unroll
                for (int half = 0; half < 2; half++) {
                    int m = r0 + half * 8;
                    int b = m >> 11, s = m & (SEQ - 1);
                    float cv = fc[s * 64 + ip];
                    float sv = fs[s * 64 + ip];
                    float xr = d[mi][nj][2 * half], xi = d[mi][nj][2 * half + 1];
                    float rr = xr * cv - xi * sv;
                    float ri = xr * sv + xi * cv;
                    if (EPI == 1) { rr *= 0.08838834764831845f; ri *= 0.08838834764831845f; }
                    __align__(8) __half o[4];
                    if (EPI == 1) {
                        __half hr = __float2half_rn(rr);
                        __half hi = __float2half_rn(ri);
                        o[0] = hr; o[1] = __float2half_rn(rr - __half2float(hr));
                        o[2] = hi; o[3] = __float2half_rn(ri - __half2float(hi));
                    } else {
                        __half hr = __float2half_rn(rr);
                        __half hi = __float2half_rn(ri);
                        o[0] = hr; o[1] = hr; o[2] = hi; o[3] = hi;
                    }
                    size_t rowo = (EPI == 1)
                        ? ((size_t)(b * NH  + h) * SEQ + s)
                        : ((size_t)(b * NKV + h) * SEQ + s);
                    __half* dp = (EPI == 1 ? g_qs2 : g_ks2) + rowo * 256 + dl * 2;
                    *(uint2*)dp = *(uint2*)o;
                }
            }
        }
    }
}

// ---------------------------------------------------------------------------
// fp16 causal flash attention (R13 core, proven); epilogue writes fp16 g_as.
// ---------------------------------------------------------------------------
#define SQ_STR   528
#define SK_STR   528
#define SV_STR   272
#define SP_STR   144
#define SQ_OFF   0
#define SK_OFF   33792
#define SV_OFF   67584
#define SP_OFF   84992
#define ATT_SMEM 94208

__global__ void __launch_bounds__(256) attn_mma(
    const __half* __restrict__ Qs, const __half* __restrict__ Ks,
    const __half* __restrict__ Vs, __half* __restrict__ Oas)
{
    extern __shared__ __align__(1024) char smem[];
    const uint32_t sQ = smem_u32(smem) + SQ_OFF;
    const uint32_t sK = smem_u32(smem) + SK_OFF;
    const uint32_t sV = smem_u32(smem) + SV_OFF;
    const uint32_t sP = smem_u32(smem) + SP_OFF;
    float* mergeO = (float*)smem;
    float* mergeM = (float*)(smem + 32768);
    float* mergeL = (float*)(smem + 32768 + 256);

    const int qi = (SEQ / 64 - 1) - blockIdx.x;
    const int bh = blockIdx.y;
    const int b = bh >> 5, h = bh & 31, kvh = h >> 2;
    const int q0 = qi * 64;
    const int tid = threadIdx.x;
    const int wid = tid >> 5, lane = tid & 31;
    const int wm = wid & 3, wn = wid >> 2;
    const int grp = lane >> 3, lrow = lane & 7;

    const __half* gk = Ks + ((size_t)(b * NKV + kvh) * SEQ) * 256;
    const __half* gv = Vs + ((size_t)(b * NKV + kvh) * SEQ) * HD;

    auto load_k = [&](int t0) {
#pragma unroll
        for (int j = 0; j < 8; j++) {
            int id = tid + j * 256;
            int r = id >> 5, c = id & 31;
            cp_async16(sK + (uint32_t)(r * SK_STR + c * 16),
                       gk + ((size_t)(t0 + r)) * 256 + c * 8);
        }
        cp_commit();
    };
    auto load_v = [&](int t0) {
#pragma unroll
        for (int j = 0; j < 4; j++) {
            int id = tid + j * 256;
            int r = id >> 4, c = id & 15;
            cp_async16(sV + (uint32_t)(r * SV_STR + c * 16),
                       gv + ((size_t)(t0 + r)) * HD + c * 8);
        }
        cp_commit();
    };

    const __half* gq = Qs + ((size_t)(b * NH + h) * SEQ + q0) * 256;
#pragma unroll
    for (int j = 0; j < 8; j++) {
        int id = tid + j * 256;
        int r = id >> 5, c = id & 31;
        cp_async16(sQ + (uint32_t)(r * SQ_STR + c * 16), gq + (size_t)r * 256 + c * 8);
    }
    cp_commit();
    load_k(0);
    load_v(0);

    float m0 = -1e30f, m1 = -1e30f, l0 = 0.0f, l1 = 0.0f;
    float Oc[16][4];
#pragma unroll
    for (int j = 0; j < 16; j++)
#pragma unroll
        for (int q = 0; q < 4; q++) Oc[j][q] = 0.0f;

    const int ra = wm * 16 + (lane >> 2);

    for (int kt = 0; kt <= qi; kt++) {
        asm volatile("cp.async.wait_group 0;" ::: "memory");
        __syncthreads();

        float Sa[4][4];
#pragma unroll
        for (int nt = 0; nt < 4; nt++)
#pragma unroll
            for (int q = 0; q < 4; q++) Sa[nt][q] = 0.0f;

#pragma unroll
        for (int ks = 0; ks < 16; ks++) {
            uint32_t A[4];
            uint32_t aaddr = sQ + (uint32_t)((wm * 16 + lrow + ((grp & 1) << 3)) * SQ_STR
                                             + (ks * 16 + ((grp >> 1) << 3)) * 2);
            LDSM_X4(A[0], A[1], A[2], A[3], aaddr);
#pragma unroll
            for (int ntp = 0; ntp < 2; ntp++) {
                uint32_t b0, b1, b2, b3;
                uint32_t baddr = sK + (uint32_t)((wn * 32 + ntp * 16 + lrow + ((grp >> 1) << 3)) * SK_STR
                                                 + (ks * 16 + ((grp & 1) << 3)) * 2);
                LDSM_X4(b0, b1, b2, b3, baddr);
                MMA_F16(Sa[2 * ntp],     A, b0, b1);
                MMA_F16(Sa[2 * ntp + 1], A, b2, b3);
            }
        }

        __syncthreads();
        if (kt < qi) load_k((kt + 1) * 64);

        if (kt == qi) {
#pragma unroll
            for (int nt = 0; nt < 4; nt++) {
                int tb = wn * 32 + nt * 8 + 2 * (lane & 3);
                if (tb     > ra)     Sa[nt][0] = -1e30f;
                if (tb + 1 > ra)     Sa[nt][1] = -1e30f;
                if (tb     > ra + 8) Sa[nt][2] = -1e30f;
                if (tb + 1 > ra + 8) Sa[nt][3] = -1e30f;
            }
        }

        float hm0 = -1e30f, hm1 = -1e30f;
#pragma unroll
        for (int nt = 0; nt < 4; nt++) {
            hm0 = fmaxf(hm0, fmaxf(Sa[nt][0], Sa[nt][1]));
            hm1 = fmaxf(hm1, fmaxf(Sa[nt][2], Sa[nt][3]));
        }
        hm0 = fmaxf(hm0, __shfl_xor_sync(0xffffffffu, hm0, 1));
        hm0 = fmaxf(hm0, __shfl_xor_sync(0xffffffffu, hm0, 2));
        hm1 = fmaxf(hm1, __shfl_xor_sync(0xffffffffu, hm1, 1));
        hm1 = fmaxf(hm1, __shfl_xor_sync(0xffffffffu, hm1, 2));

        float mn0 = fmaxf(m0, hm0), mn1 = fmaxf(m1, hm1);
        float al0 = __expf(m0 - mn0), al1 = __expf(m1 - mn1);
        m0 = mn0; m1 = mn1;

        float hs0 = 0.0f, hs1 = 0.0f;
#pragma unroll
        for (int nt = 0; nt < 4; nt++) {
            Sa[nt][0] = __expf(Sa[nt][0] - mn0); hs0 += Sa[nt][0];
            Sa[nt][1] = __expf(Sa[nt][1] - mn0); hs0 += Sa[nt][1];
            Sa[nt][2] = __expf(Sa[nt][2] - mn1); hs1 += Sa[nt][2];
            Sa[nt][3] = __expf(Sa[nt][3] - mn1); hs1 += Sa[nt][3];
        }
        hs0 += __shfl_xor_sync(0xffffffffu, hs0, 1);
        hs0 += __shfl_xor_sync(0xffffffffu, hs0, 2);
        hs1 += __shfl_xor_sync(0xffffffffu, hs1, 1);
        hs1 += __shfl_xor_sync(0xffffffffu, hs1, 2);
        l0 = l0 * al0 + hs0;
        l1 = l1 * al1 + hs1;
#pragma unroll
        for (int j = 0; j < 16; j++) {
            Oc[j][0] *= al0; Oc[j][1] *= al0;
            Oc[j][2] *= al1; Oc[j][3] *= al1;
        }

        __syncwarp();
#pragma unroll
        for (int nt = 0; nt < 4; nt++) {
            int tl0 = wn * 32 + nt * 8 + 2 * (lane & 3);
#pragma unroll
            for (int q = 0; q < 4; q++) {
                int row = ra + ((q >> 1) << 3);
                int t = tl0 + (q & 1);
                uint16_t pv = __half_as_ushort(__float2half_rn(Sa[nt][q]));
                uint32_t ad = sP + (uint32_t)(row * SP_STR + t * 2);
                asm volatile("st.shared.u16 [%0], %1;" :: "r"(ad), "h"(pv));
            }
        }
        __syncwarp();

#pragma unroll
        for (int ks2 = 0; ks2 < 2; ks2++) {
            uint32_t A[4];
            uint32_t aaddr = sP + (uint32_t)((wm * 16 + lrow + ((grp & 1) << 3)) * SP_STR
                                             + (wn * 32 + ks2 * 16 + ((grp >> 1) << 3)) * 2);
            LDSM_X4(A[0], A[1], A[2], A[3], aaddr);
#pragma unroll
            for (int ntp = 0; ntp < 8; ntp++) {
                uint32_t b0, b1, b2, b3;
                uint32_t baddr = sV + (uint32_t)((wn * 32 + ks2 * 16 + lrow + ((grp & 1) << 3)) * SV_STR
                                                 + (ntp * 16 + ((grp >> 1) << 3)) * 2);
                LDSM_X4_T(b0, b1, b2, b3, baddr);
                MMA_F16(Oc[2 * ntp],     A, b0, b1);
                MMA_F16(Oc[2 * ntp + 1], A, b2, b3);
            }
        }

        __syncthreads();
        if (kt < qi) load_v((kt + 1) * 64);
    }

    // ---- merge t-halves, write fp16 g_as ----
    __syncthreads();
    if (wn == 1) {
#pragma unroll
        for (int nt = 0; nt < 16; nt++) {
            int col = nt * 8 + 2 * (lane & 3);
            *(float2*)&mergeO[ra * 128 + col]       = make_float2(Oc[nt][0], Oc[nt][1]);
            *(float2*)&mergeO[(ra + 8) * 128 + col] = make_float2(Oc[nt][2], Oc[nt][3]);
        }
        if ((lane & 3) == 0) {
            mergeM[ra] = m0;     mergeM[ra + 8] = m1;
            mergeL[ra] = l0;     mergeL[ra + 8] = l1;
        }
    }
    __syncthreads();
    if (wn == 0) {
        float M1a = mergeM[ra],     L1a = mergeL[ra];
        float M1b = mergeM[ra + 8], L1b = mergeL[ra + 8];
        float Ma = fmaxf(m0, M1a);
        float w0a = __expf(m0 - Ma), w1a = __expf(M1a - Ma);
        float inva = 1.0f / (l0 * w0a + L1a * w1a);
        float Mb = fmaxf(m1, M1b);
        float w0b = __expf(m1 - Mb), w1b = __expf(M1b - Mb);
        float invb = 1.0f / (l1 * w0b + L1b * w1b);

        const size_t r0g = (size_t)(b * SEQ + q0 + ra);
#pragma unroll
        for (int nt = 0; nt < 16; nt++) {
            int col = nt * 8 + 2 * (lane & 3);
            float2 o1a = *(float2*)&mergeO[ra * 128 + col];
            float2 o1b = *(float2*)&mergeO[(ra + 8) * 128 + col];
            float oa0 = (Oc[nt][0] * w0a + o1a.x * w1a) * inva;
            float oa1 = (Oc[nt][1] * w0a + o1a.y * w1a) * inva;
            float ob0 = (Oc[nt][2] * w0b + o1b.x * w1b) * invb;
            float ob1 = (Oc[nt][3] * w0b + o1b.y * w1b) * invb;
            int cg = h * HD + col;
            *(__half2*)&Oas[r0g * DIM + cg]       = __floats2half2_rn(oa0, oa1);
            *(__half2*)&Oas[(r0g + 8) * DIM + cg] = __floats2half2_rn(ob0, ob1);
        }
    }
}

// ---------------------------------------------------------------------------
extern "C" void kernel_launch(void* const* d_in, const int* in_sizes, int n_in,
                              void* d_out, int out_size)
{
    const float* x  = (const float*)d_in[0];
    const float* wq = (const float*)d_in[1];
    const float* wk = (const float*)d_in[2];
    const float* wv = (const float*)d_in[3];
    const float* wo = (const float*)d_in[4];
    const float* fc = (const float*)d_in[5];
    const float* fs = (const float*)d_in[6];
    float* out = (float*)d_out;

    __half *xs, *as, *wqs, *wks, *wvs, *wos, *qs2, *ks2, *vs2;
    cudaGetSymbolAddress((void**)&xs, g_xs);
    cudaGetSymbolAddress((void**)&as, g_as);
    cudaGetSymbolAddress((void**)&wqs, g_wqs);
    cudaGetSymbolAddress((void**)&wks, g_wks);
    cudaGetSymbolAddress((void**)&wvs, g_wvs);
    cudaGetSymbolAddress((void**)&wos, g_wos);
    cudaGetSymbolAddress((void**)&qs2, g_qs2);
    cudaGetSymbolAddress((void**)&ks2, g_ks2);
    cudaGetSymbolAddress((void**)&vs2, g_vs2);

    cudaFuncSetAttribute(gemm_hmma<0>, cudaFuncAttributeMaxDynamicSharedMemorySize, GSMEM);
    cudaFuncSetAttribute(gemm_hmma<1>, cudaFuncAttributeMaxDynamicSharedMemorySize, GSMEM);
    cudaFuncSetAttribute(gemm_hmma<2>, cudaFuncAttributeMaxDynamicSharedMemorySize, GSMEM);
    cudaFuncSetAttribute(gemm_hmma<3>, cudaFuncAttributeMaxDynamicSharedMemorySize, GSMEM);
    cudaFuncSetAttribute(attn_mma, cudaFuncAttributeMaxDynamicSharedMemorySize, ATT_SMEM);

    // fp16 conversions (inputs/weights only)
    cvt_f16<<<(MROWS * KDIM / 8) / 256, 256>>>(x,  xs);
    cvt_f16<<<(DIM   * KDIM / 8) / 256, 256>>>(wq, wqs);
    cvt_f16<<<(KVDIM * KDIM / 8) / 256, 256>>>(wk, wks);
    cvt_f16<<<(KVDIM * KDIM / 8) / 256, 256>>>(wv, wvs);
    cvt_f16<<<(DIM   * KDIM / 8) / 256, 256>>>(wo, wos);

    // QKV projections with fused rope/pack epilogues
    gemm_hmma<1><<<dim3(DIM   / 128, MROWS / 128), 256, GSMEM>>>(xs, wqs, nullptr, fc, fs, DIM);
    gemm_hmma<2><<<dim3(KVDIM / 128, MROWS / 128), 256, GSMEM>>>(xs, wks, nullptr, fc, fs, KVDIM);
    gemm_hmma<3><<<dim3(KVDIM / 128, MROWS / 128), 256, GSMEM>>>(xs, wvs, nullptr, fc, fs, KVDIM);

    // fp16 flash attention (epilogue writes fp16 g_as)
    attn_mma<<<dim3(SEQ / 64, BATCH * NH), 256, ATT_SMEM>>>(qs2, ks2, vs2, as);

    // Output projection (fp32 epilogue)
    gemm_hmma<0><<<dim3(DIM / 128, MROWS / 128), 256, GSMEM>>>(as, wos, out, fc, fs, DIM);
}